// round 3
// baseline (speedup 1.0000x reference)
#include <cuda_runtime.h>
#include <cooperative_groups.h>

namespace cg = cooperative_groups;

#define B_    256
#define T_    512
#define DIN   128
#define H_    512
#define DOUT  64

#define CLUSTER 8
#define BB      16            // batch rows per cluster
#define CPT     64            // Wrec columns per CTA
#define HSTR    516           // padded h row stride (floats) -> 2-phase LDS.128
#define HB2     (BB*HSTR)     // one h buffer (floats)

// shared-memory float offsets (rnn kernel)
#define OFF_WS   0
#define OFF_HB   (H_*CPT)                 // 32768
#define SMEM_FLOATS (OFF_HB + 2*HB2)      // 32768 + 16512 = 49280
#define SMEM_RNN_BYTES (SMEM_FLOATS * 4)  // 197,120 B < 227 KB

// 268 MB scratch: precomputed input projections, [B][T][H] as float4
__device__ float4 g_xproj4[(size_t)B_ * T_ * H_ / 4];
// 268 MB scratch: hidden-state history, [B][T][H] as float4
__device__ float4 g_hist4[(size_t)B_ * T_ * H_ / 4];

// ---------------------------------------------------------------------------
// f32x2 packed-fp32 helpers (sm_100+ PTX). Bit-identical .rn rounding.
// ---------------------------------------------------------------------------
__device__ __forceinline__ unsigned long long pack2(float lo, float hi) {
    unsigned long long r;
    asm("mov.b64 %0, {%1, %2};" : "=l"(r) : "f"(lo), "f"(hi));
    return r;
}
__device__ __forceinline__ unsigned long long bcast2(float v) {
    unsigned long long r;
    asm("mov.b64 %0, {%1, %1};" : "=l"(r) : "f"(v));
    return r;
}
__device__ __forceinline__ void unpack2(unsigned long long p, float& lo, float& hi) {
    asm("mov.b64 {%0, %1}, %2;" : "=f"(lo), "=f"(hi) : "l"(p));
}
__device__ __forceinline__ unsigned long long fma2(
    unsigned long long a, unsigned long long b, unsigned long long c) {
    unsigned long long d;
    asm("fma.rn.f32x2 %0, %1, %2, %3;" : "=l"(d) : "l"(a), "l"(b), "l"(c));
    return d;
}
__device__ __forceinline__ unsigned long long add2(
    unsigned long long a, unsigned long long b) {
    unsigned long long d;
    asm("add.rn.f32x2 %0, %1, %2;" : "=l"(d) : "l"(a), "l"(b));
    return d;
}

// tanh via EX2+RCP: abs err ~1e-7, saturates correctly at +/-inf.
__device__ __forceinline__ float tanh_fast(float x) {
    float e = __expf(2.0f * x);
    return 1.0f - 2.0f / (e + 1.0f);
}

// ---------------------------------------------------------------------------
// Kernel 1: xproj[b,t,:] = inputs[b,t,:] @ Win + brec   ([131072,128]@[128,512])
// BM=64, BN=64, BK=128 (whole K). f32x2 mainloop, swizzled A-transpose tile.
// ---------------------------------------------------------------------------
__global__ __launch_bounds__(256) void xproj_kernel(
    const float* __restrict__ X, const float* __restrict__ Win,
    const float* __restrict__ brec)
{
    extern __shared__ float smx[];
    float* Ast = smx;          // [128][64] k-major, XOR-swizzled r-groups
    float* Bs  = smx + 8192;   // [128][64]

    const int tid = threadIdx.x;
    const int bt0 = blockIdx.x * 64;
    const int n0  = blockIdx.y * 64;

    const float4* X4 = reinterpret_cast<const float4*>(X);
    const float4* W4 = reinterpret_cast<const float4*>(Win);

    // load & transpose A tile with swizzle: logical A[k][r] = X[bt0+r][k]
    // addr(k, r) = k*64 + (((r>>2) ^ ((k>>2)&15))<<2) + (r&3)
#pragma unroll
    for (int i = 0; i < 8; i++) {
        int lin = i * 256 + tid;
        int r = lin >> 5, kq = lin & 31;
        float4 v = X4[(size_t)(bt0 + r) * (DIN / 4) + kq];
        int sw = (((r >> 2) ^ (kq & 15)) << 2) + (r & 3);
        int base = kq * 256;                 // (kq*4) * 64
        Ast[base +   0 + sw] = v.x;
        Ast[base +  64 + sw] = v.y;
        Ast[base + 128 + sw] = v.z;
        Ast[base + 192 + sw] = v.w;
    }
    // load B tile: Win[k][n0 + n]
#pragma unroll
    for (int i = 0; i < 8; i++) {
        int lin = i * 256 + tid;
        int k = lin >> 4, nq = lin & 15;
        *reinterpret_cast<float4*>(&Bs[k * 64 + nq * 4]) =
            W4[(size_t)k * (H_ / 4) + (n0 >> 2) + nq];
    }
    __syncthreads();

    const int ty = tid >> 4, tx = tid & 15;
    unsigned long long a01[4] = {0ull, 0ull, 0ull, 0ull};
    unsigned long long a23[4] = {0ull, 0ull, 0ull, 0ull};

#pragma unroll 8
    for (int k = 0; k < 128; k++) {
        int kg = (k >> 2) & 15;
        float4 a = *reinterpret_cast<const float4*>(
            &Ast[k * 64 + ((ty ^ kg) << 2)]);
        ulonglong2 bv = *reinterpret_cast<const ulonglong2*>(
            &Bs[k * 64 + tx * 4]);
        unsigned long long s0 = bcast2(a.x), s1 = bcast2(a.y),
                           s2 = bcast2(a.z), s3 = bcast2(a.w);
        a01[0] = fma2(s0, bv.x, a01[0]);  a23[0] = fma2(s0, bv.y, a23[0]);
        a01[1] = fma2(s1, bv.x, a01[1]);  a23[1] = fma2(s1, bv.y, a23[1]);
        a01[2] = fma2(s2, bv.x, a01[2]);  a23[2] = fma2(s2, bv.y, a23[2]);
        a01[3] = fma2(s3, bv.x, a01[3]);  a23[3] = fma2(s3, bv.y, a23[3]);
    }

    const float4 br = *reinterpret_cast<const float4*>(brec + n0 + tx * 4);
#pragma unroll
    for (int i = 0; i < 4; i++) {
        float f0, f1, f2, f3;
        unpack2(a01[i], f0, f1);
        unpack2(a23[i], f2, f3);
        float4 o;
        o.x = f0 + br.x; o.y = f1 + br.y; o.z = f2 + br.z; o.w = f3 + br.w;
        g_xproj4[(size_t)(bt0 + ty * 4 + i) * (H_ / 4) + (n0 >> 2) + tx] = o;
    }
}

// ---------------------------------------------------------------------------
// Kernel 2: persistent clustered recurrence (serial path ONLY).
// Cluster of 8 CTAs = one 16-batch tile; CTA rank owns Wrec cols [rank*64,+64)
// resident in SMEM all 512 steps. Per step: rec slice (f32x2) -> tanh ->
// DSMEM push to all peers (double-buffered) -> STG h slice to g_hist ->
// ONE cluster.sync. Output GEMM happens in a separate parallel kernel.
// ---------------------------------------------------------------------------
__global__ void __cluster_dims__(CLUSTER, 1, 1) __launch_bounds__(256, 1)
rnn_kernel(const float* __restrict__ Wrec, const float* __restrict__ h0)
{
    extern __shared__ float sm[];
    float* Ws  = sm + OFF_WS;   // [512][64]   Wrec column slice
    float* hb  = sm + OFF_HB;   // [2][16][516] double-buffered full h

    cg::cluster_group cluster = cg::this_cluster();
    const int rank = (int)cluster.block_rank();
    const int cid  = blockIdx.x / CLUSTER;
    const int tid  = threadIdx.x;
    const int gb0  = cid * BB;
    const int col0 = rank * CPT;

    // ---- one-time SMEM fills ----
    const float4* Wrec4 = reinterpret_cast<const float4*>(Wrec);
    for (int lin = tid; lin < H_ * CPT / 4; lin += 256) {
        int r = lin >> 4, q = lin & 15;
        *reinterpret_cast<float4*>(&Ws[r * CPT + q * 4]) =
            Wrec4[(size_t)r * (H_ / 4) + rank * 16 + q];
    }
    for (int lin = tid; lin < HB2; lin += 256) {
        int k = lin % HSTR;
        hb[lin] = (k < H_) ? h0[k] : 0.f;   // buffer 0 <- h0, pads 0
    }
    __syncthreads();
    cluster.sync();

    // ---- thread mapping: tid = c4*16 + b ----
    const int b  = tid & 15;
    const int c4 = tid >> 4;

    // peer pointers for the h_new slice push (one float4 per thread per rank)
    float* myslot = hb + b * HSTR + col0 + c4 * 4;
    float* peer[CLUSTER];
#pragma unroll
    for (int r = 0; r < CLUSTER; r++)
        peer[r] = cluster.map_shared_rank(myslot, r);

    // Wrec slice as packed-pair view: wq[k*16] = cols (c4*4, c4*4+1) of row k
    const ulonglong2* wq = reinterpret_cast<const ulonglong2*>(Ws) + c4;

    const float4* xptr = g_xproj4 + (size_t)(gb0 + b) * T_ * (H_ / 4)
                         + rank * 16 + c4;
    float4* hptr = g_hist4 + (size_t)(gb0 + b) * T_ * (H_ / 4)
                         + rank * 16 + c4;
    float4 xpn = xptr[0];   // xp prefetch (one step ahead)

    int cur = 0;
    for (int t = 0; t < T_; t++) {
        float4 xp = xpn;
        if (t + 1 < T_) xpn = xptr[(size_t)(t + 1) * (H_ / 4)];

        // rec: acc[c] = xp[c] + sum_k h[b][k] * Wrec[k][col0 + c4*4 + c]
        const float4* hrow =
            reinterpret_cast<const float4*>(hb + cur * HB2 + b * HSTR);
        unsigned long long axy0 = pack2(xp.x, xp.y);
        unsigned long long azw0 = pack2(xp.z, xp.w);
        unsigned long long axy1 = 0ull, azw1 = 0ull;
#pragma unroll 8
        for (int kq = 0; kq < H_ / 4; kq++) {
            float4 h4 = hrow[kq];
            const ulonglong2* wr = wq + (kq << 6);   // 4 rows * 16 u2/row
            ulonglong2 w0 = wr[0];
            ulonglong2 w1 = wr[16];
            ulonglong2 w2 = wr[32];
            ulonglong2 w3 = wr[48];
            unsigned long long hx = bcast2(h4.x), hy = bcast2(h4.y),
                               hz = bcast2(h4.z), hw = bcast2(h4.w);
            axy0 = fma2(hx, w0.x, axy0);  azw0 = fma2(hx, w0.y, azw0);
            axy1 = fma2(hy, w1.x, axy1);  azw1 = fma2(hy, w1.y, azw1);
            axy0 = fma2(hz, w2.x, axy0);  azw0 = fma2(hz, w2.y, azw0);
            axy1 = fma2(hw, w3.x, axy1);  azw1 = fma2(hw, w3.y, azw1);
        }
        unsigned long long axy = add2(axy0, axy1);
        unsigned long long azw = add2(azw0, azw1);
        float ax, ay, az, aw;
        unpack2(axy, ax, ay);
        unpack2(azw, az, aw);

        float4 hn;
        hn.x = tanh_fast(ax); hn.y = tanh_fast(ay);
        hn.z = tanh_fast(az); hn.w = tanh_fast(aw);

        // push h_new slice to every cluster CTA's next buffer (incl. self)
        const int nxt  = cur ^ 1;
        const int foff = nxt * HB2;
#pragma unroll
        for (int r = 0; r < CLUSTER; r++)
            *reinterpret_cast<float4*>(peer[r] + foff) = hn;

        // record h_t for the parallel output GEMM (fire-and-forget STG.128)
        hptr[(size_t)t * (H_ / 4)] = hn;

        cluster.sync();   // release pushes, acquire peers' pushes

        cur = nxt;
    }
}

// ---------------------------------------------------------------------------
// Kernel 3: out[bt][o] = g_hist[bt][:] @ Wout + bout   ([131072,512]@[512,64])
// BM=64, BN=64 (=DOUT), BK=128 x 4 chunks. Same tile scheme as xproj.
// ---------------------------------------------------------------------------
__global__ __launch_bounds__(256) void out_gemm_kernel(
    const float* __restrict__ Wout, const float* __restrict__ bout,
    float* __restrict__ out)
{
    extern __shared__ float smx[];
    float* Ast = smx;          // [128][64] k-major, XOR-swizzled r-groups
    float* Bs  = smx + 8192;   // [128][64]

    const int tid = threadIdx.x;
    const int bt0 = blockIdx.x * 64;
    const int ty = tid >> 4, tx = tid & 15;

    const float4* A4 = g_hist4;                       // [131072][128] float4
    const float4* W4 = reinterpret_cast<const float4*>(Wout);

    unsigned long long a01[4] = {0ull, 0ull, 0ull, 0ull};
    unsigned long long a23[4] = {0ull, 0ull, 0ull, 0ull};

    for (int kc = 0; kc < H_ / 128; kc++) {
        // load & transpose A chunk: A[k][r] = hist[bt0+r][kc*128 + k]
#pragma unroll
        for (int i = 0; i < 8; i++) {
            int lin = i * 256 + tid;
            int r = lin >> 5, kq = lin & 31;
            float4 v = A4[(size_t)(bt0 + r) * (H_ / 4) + kc * 32 + kq];
            int sw = (((r >> 2) ^ (kq & 15)) << 2) + (r & 3);
            int base = kq * 256;
            Ast[base +   0 + sw] = v.x;
            Ast[base +  64 + sw] = v.y;
            Ast[base + 128 + sw] = v.z;
            Ast[base + 192 + sw] = v.w;
        }
        // load B chunk: Wout[kc*128 + k][n]
#pragma unroll
        for (int i = 0; i < 8; i++) {
            int lin = i * 256 + tid;
            int k = lin >> 4, nq = lin & 15;
            *reinterpret_cast<float4*>(&Bs[k * 64 + nq * 4]) =
                W4[(size_t)(kc * 128 + k) * (DOUT / 4) + nq];
        }
        __syncthreads();

#pragma unroll 8
        for (int k = 0; k < 128; k++) {
            int kg = (k >> 2) & 15;
            float4 a = *reinterpret_cast<const float4*>(
                &Ast[k * 64 + ((ty ^ kg) << 2)]);
            ulonglong2 bv = *reinterpret_cast<const ulonglong2*>(
                &Bs[k * 64 + tx * 4]);
            unsigned long long s0 = bcast2(a.x), s1 = bcast2(a.y),
                               s2 = bcast2(a.z), s3 = bcast2(a.w);
            a01[0] = fma2(s0, bv.x, a01[0]);  a23[0] = fma2(s0, bv.y, a23[0]);
            a01[1] = fma2(s1, bv.x, a01[1]);  a23[1] = fma2(s1, bv.y, a23[1]);
            a01[2] = fma2(s2, bv.x, a01[2]);  a23[2] = fma2(s2, bv.y, a23[2]);
            a01[3] = fma2(s3, bv.x, a01[3]);  a23[3] = fma2(s3, bv.y, a23[3]);
        }
        __syncthreads();
    }

    const float4 br = *reinterpret_cast<const float4*>(bout + tx * 4);
    float4* O4 = reinterpret_cast<float4*>(out);
#pragma unroll
    for (int i = 0; i < 4; i++) {
        float f0, f1, f2, f3;
        unpack2(a01[i], f0, f1);
        unpack2(a23[i], f2, f3);
        float4 o;
        o.x = f0 + br.x; o.y = f1 + br.y; o.z = f2 + br.z; o.w = f3 + br.w;
        O4[(size_t)(bt0 + ty * 4 + i) * (DOUT / 4) + tx] = o;
    }
}

// ---------------------------------------------------------------------------
extern "C" void kernel_launch(void* const* d_in, const int* in_sizes, int n_in,
                              void* d_out, int out_size)
{
    (void)in_sizes; (void)n_in; (void)out_size;
    const float* X    = (const float*)d_in[0];
    const float* Win  = (const float*)d_in[1];
    const float* Wrec = (const float*)d_in[2];
    const float* brec = (const float*)d_in[3];
    const float* Wout = (const float*)d_in[4];
    const float* bout = (const float*)d_in[5];
    const float* h0   = (const float*)d_in[6];
    float* out = (float*)d_out;

    cudaFuncSetAttribute(xproj_kernel,
        cudaFuncAttributeMaxDynamicSharedMemorySize, 65536);
    cudaFuncSetAttribute(rnn_kernel,
        cudaFuncAttributeMaxDynamicSharedMemorySize, SMEM_RNN_BYTES);
    cudaFuncSetAttribute(out_gemm_kernel,
        cudaFuncAttributeMaxDynamicSharedMemorySize, 65536);

    dim3 g1(B_ * T_ / 64, H_ / 64);                 // 2048 x 8
    xproj_kernel<<<g1, 256, 65536>>>(X, Win, brec);

    rnn_kernel<<<(B_ / BB) * CLUSTER, 256, SMEM_RNN_BYTES>>>(Wrec, h0);

    out_gemm_kernel<<<B_ * T_ / 64, 256, 65536>>>(Wout, bout, out);
}

// round 15
// speedup vs baseline: 1.1018x; 1.1018x over previous
#include <cuda_runtime.h>
#include <cooperative_groups.h>
#include <cstdint>

namespace cg = cooperative_groups;

#define B_    256
#define T_    512
#define DIN   128
#define H_    512
#define DOUT  64

#define CLUSTER 8
#define BB      16            // batch rows per cluster
#define CPT     64            // Wrec columns per CTA
#define WSTR    516           // padded Wt row stride (floats): kills c4-group bank conflicts
#define HPAD    68            // padded per-(rank,b) h row (floats): 2-phase LDS.128
#define INB     (BB*HPAD)     // 1088 floats per rank block
#define INBUF   (CLUSTER*INB) // 8704 floats per h buffer
#define SLICE_BYTES (INB*4)   // 4352 B per rank slice
#define FULL_TX (CLUSTER*SLICE_BYTES) // 34816 B expected per full-barrier phase

// smem float offsets (rnn kernel)
#define OFF_WT    0                      // Wt[64][516] transposed Wrec slice
#define OFF_IN    (CPT*WSTR)             // 33024: in[2][8][16][68]
#define OFF_STAGE (OFF_IN + 2*INBUF)     // 50432: stage[16][68]
#define SMEM_FLOATS (OFF_STAGE + INB)    // 51520
#define BAR_BYTE_OFF (SMEM_FLOATS*4)     // 206080 (16B aligned)
#define SMEM_RNN_BYTES (BAR_BYTE_OFF + 64)   // 206144 < 227KB

// 268 MB scratch: precomputed input projections, [B][T][H] as float4
__device__ float4 g_xproj4[(size_t)B_ * T_ * H_ / 4];
// 268 MB scratch: hidden-state history, [B][T][H] as float4
__device__ float4 g_hist4[(size_t)B_ * T_ * H_ / 4];

// ---------------------------------------------------------------------------
// f32x2 packed helpers + misc PTX
// ---------------------------------------------------------------------------
__device__ __forceinline__ unsigned long long bcast2(float v) {
    unsigned long long r;
    asm("mov.b64 %0, {%1, %1};" : "=l"(r) : "f"(v));
    return r;
}
__device__ __forceinline__ void unpack2(unsigned long long p, float& lo, float& hi) {
    asm("mov.b64 {%0, %1}, %2;" : "=f"(lo), "=f"(hi) : "l"(p));
}
__device__ __forceinline__ unsigned long long fma2(
    unsigned long long a, unsigned long long b, unsigned long long c) {
    unsigned long long d;
    asm("fma.rn.f32x2 %0, %1, %2, %3;" : "=l"(d) : "l"(a), "l"(b), "l"(c));
    return d;
}
__device__ __forceinline__ unsigned long long add2(
    unsigned long long a, unsigned long long b) {
    unsigned long long d;
    asm("add.rn.f32x2 %0, %1, %2;" : "=l"(d) : "l"(a), "l"(b));
    return d;
}
__device__ __forceinline__ float tanh_fast(float x) {
    float e = __expf(2.0f * x);
    return 1.0f - 2.0f / (e + 1.0f);
}
__device__ __forceinline__ uint32_t smem_u32(const void* p) {
    uint32_t a;
    asm("{ .reg .u64 t; cvta.to.shared.u64 t, %1; cvt.u32.u64 %0, t; }"
        : "=r"(a) : "l"(p));
    return a;
}
__device__ __forceinline__ uint32_t mapa_u32(uint32_t a, uint32_t rank) {
    uint32_t d;
    asm("mapa.shared::cluster.u32 %0, %1, %2;" : "=r"(d) : "r"(a), "r"(rank));
    return d;
}

#define MBAR_INIT(a, c) \
    asm volatile("mbarrier.init.shared.b64 [%0], %1;" :: "r"(a), "r"(c) : "memory")
#define MBAR_ARRIVE_EXPECT_TX(a, bytes) \
    asm volatile("mbarrier.arrive.expect_tx.shared.b64 _, [%0], %1;" \
                 :: "r"(a), "r"(bytes) : "memory")
#define MBAR_ARRIVE_REMOTE(a, rank) \
    asm volatile("{ .reg .b32 ra; mapa.shared::cluster.u32 ra, %0, %1;" \
                 "  mbarrier.arrive.shared::cluster.b64 _, [ra]; }" \
                 :: "r"(a), "r"(rank) : "memory")

__device__ __forceinline__ void mbar_wait(uint32_t mbar, uint32_t parity) {
    uint32_t done;
    asm volatile(
        "{ .reg .pred p;"
        "  mbarrier.try_wait.parity.acquire.cta.shared::cta.b64 p, [%1], %2;"
        "  selp.b32 %0, 1, 0, p; }"
        : "=r"(done) : "r"(mbar), "r"(parity) : "memory");
    if (!done) {
        asm volatile(
            "{ .reg .pred P1;"
            "WAIT_%=:"
            "  mbarrier.try_wait.parity.acquire.cta.shared::cta.b64 P1, [%0], %1, 0x989680;"
            "  @P1 bra.uni DONE_%=;"
            "  bra.uni WAIT_%=;"
            "DONE_%=: }"
            :: "r"(mbar), "r"(parity) : "memory");
    }
}

#define CLUSTER_SYNC_ASM() do { \
    asm volatile("barrier.cluster.arrive.aligned;" ::: "memory"); \
    asm volatile("barrier.cluster.wait.aligned;" ::: "memory"); \
} while (0)

// ---------------------------------------------------------------------------
// Kernel 1: xproj[b,t,:] = inputs[b,t,:] @ Win + brec   ([131072,128]@[128,512])
// (unchanged — measured 480us, fma-bound)
// ---------------------------------------------------------------------------
__global__ __launch_bounds__(256) void xproj_kernel(
    const float* __restrict__ X, const float* __restrict__ Win,
    const float* __restrict__ brec)
{
    extern __shared__ float smx[];
    float* Ast = smx;          // [128][64] k-major, XOR-swizzled r-groups
    float* Bs  = smx + 8192;   // [128][64]

    const int tid = threadIdx.x;
    const int bt0 = blockIdx.x * 64;
    const int n0  = blockIdx.y * 64;

    const float4* X4 = reinterpret_cast<const float4*>(X);
    const float4* W4 = reinterpret_cast<const float4*>(Win);

#pragma unroll
    for (int i = 0; i < 8; i++) {
        int lin = i * 256 + tid;
        int r = lin >> 5, kq = lin & 31;
        float4 v = X4[(size_t)(bt0 + r) * (DIN / 4) + kq];
        int sw = (((r >> 2) ^ (kq & 15)) << 2) + (r & 3);
        int base = kq * 256;
        Ast[base +   0 + sw] = v.x;
        Ast[base +  64 + sw] = v.y;
        Ast[base + 128 + sw] = v.z;
        Ast[base + 192 + sw] = v.w;
    }
#pragma unroll
    for (int i = 0; i < 8; i++) {
        int lin = i * 256 + tid;
        int k = lin >> 4, nq = lin & 15;
        *reinterpret_cast<float4*>(&Bs[k * 64 + nq * 4]) =
            W4[(size_t)k * (H_ / 4) + (n0 >> 2) + nq];
    }
    __syncthreads();

    const int ty = tid >> 4, tx = tid & 15;
    unsigned long long a01[4] = {0ull, 0ull, 0ull, 0ull};
    unsigned long long a23[4] = {0ull, 0ull, 0ull, 0ull};

#pragma unroll 8
    for (int k = 0; k < 128; k++) {
        int kg = (k >> 2) & 15;
        float4 a = *reinterpret_cast<const float4*>(
            &Ast[k * 64 + ((ty ^ kg) << 2)]);
        ulonglong2 bv = *reinterpret_cast<const ulonglong2*>(
            &Bs[k * 64 + tx * 4]);
        unsigned long long s0 = bcast2(a.x), s1 = bcast2(a.y),
                           s2 = bcast2(a.z), s3 = bcast2(a.w);
        a01[0] = fma2(s0, bv.x, a01[0]);  a23[0] = fma2(s0, bv.y, a23[0]);
        a01[1] = fma2(s1, bv.x, a01[1]);  a23[1] = fma2(s1, bv.y, a23[1]);
        a01[2] = fma2(s2, bv.x, a01[2]);  a23[2] = fma2(s2, bv.y, a23[2]);
        a01[3] = fma2(s3, bv.x, a01[3]);  a23[3] = fma2(s3, bv.y, a23[3]);
    }

    const float4 br = *reinterpret_cast<const float4*>(brec + n0 + tx * 4);
#pragma unroll
    for (int i = 0; i < 4; i++) {
        float f0, f1, f2, f3;
        unpack2(a01[i], f0, f1);
        unpack2(a23[i], f2, f3);
        float4 o;
        o.x = f0 + br.x; o.y = f1 + br.y; o.z = f2 + br.z; o.w = f3 + br.w;
        g_xproj4[(size_t)(bt0 + ty * 4 + i) * (H_ / 4) + (n0 >> 2) + tx] = o;
    }
}

// ---------------------------------------------------------------------------
// Kernel 2: persistent clustered recurrence, mbarrier-pipelined DSMEM comm.
// State in[buf][r][b][68]; weights Wt[c][k] transposed w/ padded stride 516.
// Rec GEMM k-vectorized: fma2 consumes LDS.128 pairs directly.
// Per step: [wait full(cur), re-arm] -> rec -> [bulk-read guard + bar] ->
// stage STS + hist STG -> [bar] -> threads 0-7 (thread r handles rank r):
// remote empty arrive, wait empty(nxt), fence, cp.async.bulk w/ complete_tx
// on rank r's full(nxt). No cluster.sync in loop.
// ---------------------------------------------------------------------------
__global__ void __cluster_dims__(CLUSTER, 1, 1) __launch_bounds__(256, 1)
rnn_kernel(const float* __restrict__ Wrec, const float* __restrict__ h0)
{
    extern __shared__ float sm[];
    float* Wt    = sm + OFF_WT;     // [64][516]
    float* inb   = sm + OFF_IN;     // [2][8][16][68]
    float* stage = sm + OFF_STAGE;  // [16][68]

    cg::cluster_group cluster = cg::this_cluster();
    const uint32_t rank = cluster.block_rank();
    const int cid  = blockIdx.x / CLUSTER;
    const int tid  = threadIdx.x;
    const int gb0  = cid * BB;

    const uint32_t smem_base = smem_u32(sm);
    const uint32_t barBase   = smem_base + BAR_BYTE_OFF;
    const uint32_t fullBar0  = barBase;        // full[0]
    const uint32_t fullBar1  = barBase + 8;    // full[1]
    const uint32_t emptyBar0 = barBase + 16;   // empty[0]
    const uint32_t emptyBar1 = barBase + 24;   // empty[1]
    const uint32_t stageAddr = smem_base + OFF_STAGE * 4;

    // ---- one-time fills ----
    // Wt[c][k] = Wrec[k][rank*64 + c], row stride WSTR
    const float4* Wrec4 = reinterpret_cast<const float4*>(Wrec);
    for (int lin = tid; lin < H_ * 16; lin += 256) {
        int k = lin >> 4, q = lin & 15;
        float4 v = Wrec4[(size_t)k * (H_ / 4) + rank * 16 + q];
        int c = q * 4;
        Wt[(c + 0) * WSTR + k] = v.x;
        Wt[(c + 1) * WSTR + k] = v.y;
        Wt[(c + 2) * WSTR + k] = v.z;
        Wt[(c + 3) * WSTR + k] = v.w;
    }
    // in[0][r][b][j] = h0[r*64+j]
    for (int lin = tid; lin < INBUF; lin += 256) {
        int r = lin / INB;
        int rem = lin - r * INB;
        int j = rem % HPAD;
        inb[lin] = (j < 64) ? h0[r * 64 + j] : 0.f;
    }
    if (tid == 0) {
        MBAR_INIT(fullBar0, 1);
        MBAR_INIT(fullBar1, 1);
        MBAR_INIT(emptyBar0, CLUSTER);
        MBAR_INIT(emptyBar1, CLUSTER);
        MBAR_ARRIVE_EXPECT_TX(fullBar0, FULL_TX);   // pre-arm phase 0
        MBAR_ARRIVE_EXPECT_TX(fullBar1, FULL_TX);
    }
    __syncthreads();
    CLUSTER_SYNC_ASM();   // barriers + in[0] visible cluster-wide

    // ---- thread mapping: tid = c4*16 + b ----
    const int b  = tid & 15;
    const int c4 = tid >> 4;

    const ulonglong2* wt0 = reinterpret_cast<const ulonglong2*>(Wt + (c4 * 4 + 0) * WSTR);
    const ulonglong2* wt1 = reinterpret_cast<const ulonglong2*>(Wt + (c4 * 4 + 1) * WSTR);
    const ulonglong2* wt2 = reinterpret_cast<const ulonglong2*>(Wt + (c4 * 4 + 2) * WSTR);
    const ulonglong2* wt3 = reinterpret_cast<const ulonglong2*>(Wt + (c4 * 4 + 3) * WSTR);

    float* stSlot = stage + b * HPAD + c4 * 4;

    const float4* xptr = g_xproj4 + (size_t)(gb0 + b) * T_ * (H_ / 4)
                         + rank * 16 + c4;
    float4* hptr = g_hist4 + (size_t)(gb0 + b) * T_ * (H_ / 4)
                         + rank * 16 + c4;
    float4 xpn = xptr[0];

    uint32_t phF0 = 0, phF1 = 0, phE0 = 0, phE1 = 0;

    for (int t = 0; t < T_; t++) {
        const int cur = t & 1;
        const int nxt = cur ^ 1;

        // ---- wait h_t present (t=0: loaded locally), re-arm for next phase
        if (t > 0) {
            if (cur == 0) { mbar_wait(fullBar0, phF0); if (tid == 0) MBAR_ARRIVE_EXPECT_TX(fullBar0, FULL_TX); phF0 ^= 1; }
            else          { mbar_wait(fullBar1, phF1); if (tid == 0) MBAR_ARRIVE_EXPECT_TX(fullBar1, FULL_TX); phF1 ^= 1; }
        }

        float4 xp = xpn;
        if (t + 1 < T_) xpn = xptr[(size_t)(t + 1) * (H_ / 4)];

        // ---- rec GEMM slice, k-vectorized ----
        const ulonglong2* hbase = reinterpret_cast<const ulonglong2*>(
            inb + cur * INBUF + b * HPAD);
        unsigned long long a0 = 0ull, a0b = 0ull, a1 = 0ull, a1b = 0ull,
                           a2 = 0ull, a2b = 0ull, a3 = 0ull, a3b = 0ull;
#pragma unroll 1
        for (int r = 0; r < CLUSTER; r++) {
            const ulonglong2* hr = hbase + r * (INB / 4);
            const ulonglong2* w0 = wt0 + r * 16;
            const ulonglong2* w1 = wt1 + r * 16;
            const ulonglong2* w2 = wt2 + r * 16;
            const ulonglong2* w3 = wt3 + r * 16;
#pragma unroll
            for (int j = 0; j < 16; j++) {
                ulonglong2 hU = hr[j];
                ulonglong2 q0 = w0[j];
                ulonglong2 q1 = w1[j];
                ulonglong2 q2 = w2[j];
                ulonglong2 q3 = w3[j];
                a0 = fma2(hU.x, q0.x, a0);  a0b = fma2(hU.y, q0.y, a0b);
                a1 = fma2(hU.x, q1.x, a1);  a1b = fma2(hU.y, q1.y, a1b);
                a2 = fma2(hU.x, q2.x, a2);  a2b = fma2(hU.y, q2.y, a2b);
                a3 = fma2(hU.x, q3.x, a3);  a3b = fma2(hU.y, q3.y, a3b);
            }
        }
        float l0, h0v, l1, h1v, l2, h2v, l3, h3v;
        unpack2(add2(a0, a0b), l0, h0v);
        unpack2(add2(a1, a1b), l1, h1v);
        unpack2(add2(a2, a2b), l2, h2v);
        unpack2(add2(a3, a3b), l3, h3v);

        float4 hn;
        hn.x = tanh_fast(l0 + h0v + xp.x);
        hn.y = tanh_fast(l1 + h1v + xp.y);
        hn.z = tanh_fast(l2 + h2v + xp.z);
        hn.w = tanh_fast(l3 + h3v + xp.w);

        // ---- guard: previous step's bulk copies finished READING stage ----
        // (async-group state is per-thread: threads 0-7 each issued one copy)
        if (tid < CLUSTER)
            asm volatile("cp.async.bulk.wait_group.read 0;" ::: "memory");
        __syncthreads();   // also: all threads done reading in[cur]

        // stage h_new slice (contiguous [b][68] layout) + hist record
        *reinterpret_cast<float4*>(stSlot) = hn;
        hptr[(size_t)t * (H_ / 4)] = hn;
        __syncthreads();   // stage complete

        if (tid < CLUSTER) {
            const uint32_t r = (uint32_t)tid;   // thread r handles rank r
            // signal rank r: this CTA finished reading buffer `cur`
            uint32_t eb = (cur == 0) ? emptyBar0 : emptyBar1;
            MBAR_ARRIVE_REMOTE(eb, r);
            if (t < T_ - 1) {
                // backpressure: everyone done reading buffer `nxt` (step t-1)
                if (t >= 1) {
                    if (nxt == 0) { mbar_wait(emptyBar0, phE0); phE0 ^= 1; }
                    else          { mbar_wait(emptyBar1, phE1); phE1 ^= 1; }
                }
                asm volatile("fence.proxy.async.shared::cta;" ::: "memory");
                uint32_t dstLocal = smem_base +
                    (OFF_IN + nxt * INBUF + (int)rank * INB) * 4;
                uint32_t fb = (nxt == 0) ? fullBar0 : fullBar1;
                uint32_t dst = mapa_u32(dstLocal, r);
                uint32_t mb  = mapa_u32(fb, r);
                asm volatile(
                    "cp.async.bulk.shared::cluster.shared::cta"
                    ".mbarrier::complete_tx::bytes [%0], [%1], %2, [%3];"
                    :: "r"(dst), "r"(stageAddr), "r"(SLICE_BYTES), "r"(mb)
                    : "memory");
                asm volatile("cp.async.bulk.commit_group;" ::: "memory");
            }
        }
    }

    CLUSTER_SYNC_ASM();   // no CTA exits while peers' ops may target its SMEM
}

// ---------------------------------------------------------------------------
// Kernel 3: out[bt][o] = g_hist[bt][:] @ Wout + bout   ([131072,512]@[512,64])
// ---------------------------------------------------------------------------
__global__ __launch_bounds__(256) void out_gemm_kernel(
    const float* __restrict__ Wout, const float* __restrict__ bout,
    float* __restrict__ out)
{
    extern __shared__ float smx[];
    float* Ast = smx;
    float* Bs  = smx + 8192;

    const int tid = threadIdx.x;
    const int bt0 = blockIdx.x * 64;
    const int ty = tid >> 4, tx = tid & 15;

    const float4* A4 = g_hist4;
    const float4* W4 = reinterpret_cast<const float4*>(Wout);

    unsigned long long a01[4] = {0ull, 0ull, 0ull, 0ull};
    unsigned long long a23[4] = {0ull, 0ull, 0ull, 0ull};

    for (int kc = 0; kc < H_ / 128; kc++) {
#pragma unroll
        for (int i = 0; i < 8; i++) {
            int lin = i * 256 + tid;
            int r = lin >> 5, kq = lin & 31;
            float4 v = A4[(size_t)(bt0 + r) * (H_ / 4) + kc * 32 + kq];
            int sw = (((r >> 2) ^ (kq & 15)) << 2) + (r & 3);
            int base = kq * 256;
            Ast[base +   0 + sw] = v.x;
            Ast[base +  64 + sw] = v.y;
            Ast[base + 128 + sw] = v.z;
            Ast[base + 192 + sw] = v.w;
        }
#pragma unroll
        for (int i = 0; i < 8; i++) {
            int lin = i * 256 + tid;
            int k = lin >> 4, nq = lin & 15;
            *reinterpret_cast<float4*>(&Bs[k * 64 + nq * 4]) =
                W4[(size_t)(kc * 128 + k) * (DOUT / 4) + nq];
        }
        __syncthreads();

#pragma unroll 8
        for (int k = 0; k < 128; k++) {
            int kg = (k >> 2) & 15;
            float4 a = *reinterpret_cast<const float4*>(
                &Ast[k * 64 + ((ty ^ kg) << 2)]);
            ulonglong2 bv = *reinterpret_cast<const ulonglong2*>(
                &Bs[k * 64 + tx * 4]);
            unsigned long long s0 = bcast2(a.x), s1 = bcast2(a.y),
                               s2 = bcast2(a.z), s3 = bcast2(a.w);
            a01[0] = fma2(s0, bv.x, a01[0]);  a23[0] = fma2(s0, bv.y, a23[0]);
            a01[1] = fma2(s1, bv.x, a01[1]);  a23[1] = fma2(s1, bv.y, a23[1]);
            a01[2] = fma2(s2, bv.x, a01[2]);  a23[2] = fma2(s2, bv.y, a23[2]);
            a01[3] = fma2(s3, bv.x, a01[3]);  a23[3] = fma2(s3, bv.y, a23[3]);
        }
        __syncthreads();
    }

    const float4 br = *reinterpret_cast<const float4*>(bout + tx * 4);
    float4* O4 = reinterpret_cast<float4*>(out);
#pragma unroll
    for (int i = 0; i < 4; i++) {
        float f0, f1, f2, f3;
        unpack2(a01[i], f0, f1);
        unpack2(a23[i], f2, f3);
        float4 o;
        o.x = f0 + br.x; o.y = f1 + br.y; o.z = f2 + br.z; o.w = f3 + br.w;
        O4[(size_t)(bt0 + ty * 4 + i) * (DOUT / 4) + tx] = o;
    }
}

// ---------------------------------------------------------------------------
extern "C" void kernel_launch(void* const* d_in, const int* in_sizes, int n_in,
                              void* d_out, int out_size)
{
    (void)in_sizes; (void)n_in; (void)out_size;
    const float* X    = (const float*)d_in[0];
    const float* Win  = (const float*)d_in[1];
    const float* Wrec = (const float*)d_in[2];
    const float* brec = (const float*)d_in[3];
    const float* Wout = (const float*)d_in[4];
    const float* bout = (const float*)d_in[5];
    const float* h0   = (const float*)d_in[6];
    float* out = (float*)d_out;

    cudaFuncSetAttribute(xproj_kernel,
        cudaFuncAttributeMaxDynamicSharedMemorySize, 65536);
    cudaFuncSetAttribute(rnn_kernel,
        cudaFuncAttributeMaxDynamicSharedMemorySize, SMEM_RNN_BYTES);
    cudaFuncSetAttribute(out_gemm_kernel,
        cudaFuncAttributeMaxDynamicSharedMemorySize, 65536);

    dim3 g1(B_ * T_ / 64, H_ / 64);
    xproj_kernel<<<g1, 256, 65536>>>(X, Win, brec);

    rnn_kernel<<<(B_ / BB) * CLUSTER, 256, SMEM_RNN_BYTES>>>(Wrec, h0);

    out_gemm_kernel<<<B_ * T_ / 64, 256, 65536>>>(Wout, bout, out);
}

// round 16
// speedup vs baseline: 1.5039x; 1.3650x over previous
#include <cuda_runtime.h>
#include <cooperative_groups.h>
#include <cstdint>

namespace cg = cooperative_groups;

#define B_    256
#define T_    512
#define DIN   128
#define H_    512
#define DOUT  64

#define CLUSTER 8
#define BB      16              // batch rows per cluster
#define CPT     64              // Wrec columns per CTA
#define WROW    544             // Wt row: 8 k-blocks x 68 (padded per 64-k block)
#define INBSTRIDE 1092          // floats per rank block: 16*68 + 4 pad (4368B = 16 mod 128)
#define INBUF   (CLUSTER*INBSTRIDE)   // 8736 floats per h buffer
#define SLICE_BYTES (INBSTRIDE*4)     // 4368 B per rank slice
#define FULL_TX (CLUSTER*SLICE_BYTES) // 34944 B per full-barrier phase

// smem float offsets (rnn kernel)
#define OFF_WT    0                      // Wt[64][544]
#define OFF_IN    (CPT*WROW)             // 34816: in[2][8][1092]
#define OFF_STAGE (OFF_IN + 2*INBUF)     // 52288: stage[1092]
#define SMEM_FLOATS (OFF_STAGE + INBSTRIDE)  // 53380
#define BAR_BYTE_OFF (SMEM_FLOATS*4)     // 213520 (16B aligned)
#define SMEM_RNN_BYTES (BAR_BYTE_OFF + 64)   // 213584 < 227KB

// 268 MB scratch: precomputed input projections, [B][T][H] as float4
__device__ float4 g_xproj4[(size_t)B_ * T_ * H_ / 4];
// 268 MB scratch: hidden-state history, [B][T][H] as float4
__device__ float4 g_hist4[(size_t)B_ * T_ * H_ / 4];

// ---------------------------------------------------------------------------
// f32x2 packed helpers + misc PTX
// ---------------------------------------------------------------------------
__device__ __forceinline__ unsigned long long bcast2(float v) {
    unsigned long long r;
    asm("mov.b64 %0, {%1, %1};" : "=l"(r) : "f"(v));
    return r;
}
__device__ __forceinline__ void unpack2(unsigned long long p, float& lo, float& hi) {
    asm("mov.b64 {%0, %1}, %2;" : "=f"(lo), "=f"(hi) : "l"(p));
}
__device__ __forceinline__ unsigned long long fma2(
    unsigned long long a, unsigned long long b, unsigned long long c) {
    unsigned long long d;
    asm("fma.rn.f32x2 %0, %1, %2, %3;" : "=l"(d) : "l"(a), "l"(b), "l"(c));
    return d;
}
__device__ __forceinline__ unsigned long long add2(
    unsigned long long a, unsigned long long b) {
    unsigned long long d;
    asm("add.rn.f32x2 %0, %1, %2;" : "=l"(d) : "l"(a), "l"(b));
    return d;
}
__device__ __forceinline__ float tanh_fast(float x) {
    float e = __expf(2.0f * x);
    return 1.0f - 2.0f / (e + 1.0f);
}
__device__ __forceinline__ uint32_t smem_u32(const void* p) {
    uint32_t a;
    asm("{ .reg .u64 t; cvta.to.shared.u64 t, %1; cvt.u32.u64 %0, t; }"
        : "=r"(a) : "l"(p));
    return a;
}
__device__ __forceinline__ uint32_t mapa_u32(uint32_t a, uint32_t rank) {
    uint32_t d;
    asm("mapa.shared::cluster.u32 %0, %1, %2;" : "=r"(d) : "r"(a), "r"(rank));
    return d;
}

#define MBAR_INIT(a, c) \
    asm volatile("mbarrier.init.shared.b64 [%0], %1;" :: "r"(a), "r"(c) : "memory")
#define MBAR_ARRIVE_EXPECT_TX(a, bytes) \
    asm volatile("mbarrier.arrive.expect_tx.shared.b64 _, [%0], %1;" \
                 :: "r"(a), "r"(bytes) : "memory")
#define MBAR_ARRIVE_REMOTE(a, rank) \
    asm volatile("{ .reg .b32 ra; mapa.shared::cluster.u32 ra, %0, %1;" \
                 "  mbarrier.arrive.shared::cluster.b64 _, [ra]; }" \
                 :: "r"(a), "r"(rank) : "memory")

__device__ __forceinline__ void mbar_wait(uint32_t mbar, uint32_t parity) {
    uint32_t done;
    asm volatile(
        "{ .reg .pred p;"
        "  mbarrier.try_wait.parity.acquire.cta.shared::cta.b64 p, [%1], %2;"
        "  selp.b32 %0, 1, 0, p; }"
        : "=r"(done) : "r"(mbar), "r"(parity) : "memory");
    if (!done) {
        asm volatile(
            "{ .reg .pred P1;"
            "WAIT_%=:"
            "  mbarrier.try_wait.parity.acquire.cta.shared::cta.b64 P1, [%0], %1, 0x989680;"
            "  @P1 bra.uni DONE_%=;"
            "  bra.uni WAIT_%=;"
            "DONE_%=: }"
            :: "r"(mbar), "r"(parity) : "memory");
    }
}

#define CLUSTER_SYNC_ASM() do { \
    asm volatile("barrier.cluster.arrive.aligned;" ::: "memory"); \
    asm volatile("barrier.cluster.wait.aligned;" ::: "memory"); \
} while (0)

// ---------------------------------------------------------------------------
// Kernel 1: xproj[b,t,:] = inputs[b,t,:] @ Win + brec   ([131072,128]@[128,512])
// (unchanged — measured 480us, fma-bound)
// ---------------------------------------------------------------------------
__global__ __launch_bounds__(256) void xproj_kernel(
    const float* __restrict__ X, const float* __restrict__ Win,
    const float* __restrict__ brec)
{
    extern __shared__ float smx[];
    float* Ast = smx;          // [128][64] k-major, XOR-swizzled r-groups
    float* Bs  = smx + 8192;   // [128][64]

    const int tid = threadIdx.x;
    const int bt0 = blockIdx.x * 64;
    const int n0  = blockIdx.y * 64;

    const float4* X4 = reinterpret_cast<const float4*>(X);
    const float4* W4 = reinterpret_cast<const float4*>(Win);

#pragma unroll
    for (int i = 0; i < 8; i++) {
        int lin = i * 256 + tid;
        int r = lin >> 5, kq = lin & 31;
        float4 v = X4[(size_t)(bt0 + r) * (DIN / 4) + kq];
        int sw = (((r >> 2) ^ (kq & 15)) << 2) + (r & 3);
        int base = kq * 256;
        Ast[base +   0 + sw] = v.x;
        Ast[base +  64 + sw] = v.y;
        Ast[base + 128 + sw] = v.z;
        Ast[base + 192 + sw] = v.w;
    }
#pragma unroll
    for (int i = 0; i < 8; i++) {
        int lin = i * 256 + tid;
        int k = lin >> 4, nq = lin & 15;
        *reinterpret_cast<float4*>(&Bs[k * 64 + nq * 4]) =
            W4[(size_t)k * (H_ / 4) + (n0 >> 2) + nq];
    }
    __syncthreads();

    const int ty = tid >> 4, tx = tid & 15;
    unsigned long long a01[4] = {0ull, 0ull, 0ull, 0ull};
    unsigned long long a23[4] = {0ull, 0ull, 0ull, 0ull};

#pragma unroll 8
    for (int k = 0; k < 128; k++) {
        int kg = (k >> 2) & 15;
        float4 a = *reinterpret_cast<const float4*>(
            &Ast[k * 64 + ((ty ^ kg) << 2)]);
        ulonglong2 bv = *reinterpret_cast<const ulonglong2*>(
            &Bs[k * 64 + tx * 4]);
        unsigned long long s0 = bcast2(a.x), s1 = bcast2(a.y),
                           s2 = bcast2(a.z), s3 = bcast2(a.w);
        a01[0] = fma2(s0, bv.x, a01[0]);  a23[0] = fma2(s0, bv.y, a23[0]);
        a01[1] = fma2(s1, bv.x, a01[1]);  a23[1] = fma2(s1, bv.y, a23[1]);
        a01[2] = fma2(s2, bv.x, a01[2]);  a23[2] = fma2(s2, bv.y, a23[2]);
        a01[3] = fma2(s3, bv.x, a01[3]);  a23[3] = fma2(s3, bv.y, a23[3]);
    }

    const float4 br = *reinterpret_cast<const float4*>(brec + n0 + tx * 4);
#pragma unroll
    for (int i = 0; i < 4; i++) {
        float f0, f1, f2, f3;
        unpack2(a01[i], f0, f1);
        unpack2(a23[i], f2, f3);
        float4 o;
        o.x = f0 + br.x; o.y = f1 + br.y; o.z = f2 + br.z; o.w = f3 + br.w;
        g_xproj4[(size_t)(bt0 + ty * 4 + i) * (H_ / 4) + (n0 >> 2) + tx] = o;
    }
}

// ---------------------------------------------------------------------------
// Kernel 2: persistent clustered recurrence, mbarrier-pipelined DSMEM comm.
// REGISTER-TILED rec GEMM: thread (bg,cG,q) computes 4b x 8c over k-slice
// q*64..q*64+63 (= rank block q of the h buffer). Per k-quad: 4 h LDS + 8 w
// LDS -> 128 MACs (64 fma2). Cross-q reduce-scatter butterfly (3 shfl rounds)
// leaves each lane its output float4 (b = bg*4+(q&3), c4 = cG*2+(q>>2)).
// Layouts padded so every 8-lane LDS phase group hits distinct banks.
// Comm protocol identical to prior round (slice 4368B).
// ---------------------------------------------------------------------------
__global__ void __cluster_dims__(CLUSTER, 1, 1) __launch_bounds__(256, 1)
rnn_kernel(const float* __restrict__ Wrec, const float* __restrict__ h0)
{
    extern __shared__ float sm[];
    float* Wt    = sm + OFF_WT;     // [64][544]  (8 k-blocks x 68 per row)
    float* inb   = sm + OFF_IN;     // [2][8][1092]
    float* stage = sm + OFF_STAGE;  // [1092]

    cg::cluster_group cluster = cg::this_cluster();
    const uint32_t rank = cluster.block_rank();
    const int cid  = blockIdx.x / CLUSTER;
    const int tid  = threadIdx.x;
    const int gb0  = cid * BB;

    const uint32_t smem_base = smem_u32(sm);
    const uint32_t barBase   = smem_base + BAR_BYTE_OFF;
    const uint32_t fullBar0  = barBase;
    const uint32_t fullBar1  = barBase + 8;
    const uint32_t emptyBar0 = barBase + 16;
    const uint32_t emptyBar1 = barBase + 24;
    const uint32_t stageAddr = smem_base + OFF_STAGE * 4;

    // ---- one-time fills ----
    // Wt[c][kb*68 + kl] = Wrec[kb*64+kl][rank*64 + c]
    const float4* Wrec4 = reinterpret_cast<const float4*>(Wrec);
    for (int lin = tid; lin < H_ * 16; lin += 256) {
        int k = lin >> 4, qd = lin & 15;
        float4 v = Wrec4[(size_t)k * (H_ / 4) + rank * 16 + qd];
        int c = qd * 4;
        int ko = (k >> 6) * 68 + (k & 63);
        Wt[(c + 0) * WROW + ko] = v.x;
        Wt[(c + 1) * WROW + ko] = v.y;
        Wt[(c + 2) * WROW + ko] = v.z;
        Wt[(c + 3) * WROW + ko] = v.w;
    }
    // in[0][r][b*68+j] = h0[r*64+j]; pads 0
    for (int lin = tid; lin < INBUF; lin += 256) {
        int r = lin / INBSTRIDE;
        int rem = lin - r * INBSTRIDE;
        float val = 0.f;
        if (rem < BB * 68) {
            int j = rem % 68;
            if (j < 64) val = h0[r * 64 + j];
        }
        inb[lin] = val;
    }
    if (tid == 0) {
        MBAR_INIT(fullBar0, 1);
        MBAR_INIT(fullBar1, 1);
        MBAR_INIT(emptyBar0, CLUSTER);
        MBAR_INIT(emptyBar1, CLUSTER);
        MBAR_ARRIVE_EXPECT_TX(fullBar0, FULL_TX);
        MBAR_ARRIVE_EXPECT_TX(fullBar1, FULL_TX);
    }
    __syncthreads();
    CLUSTER_SYNC_ASM();

    // ---- thread mapping: tid = cG*32 + bg*8 + q ----
    const int q  = tid & 7;          // k-slice / rank block, lane bits 0-2
    const int bg = (tid >> 3) & 3;   // 4-b group
    const int cG = tid >> 5;         // 8-col group

    // output assignment (post-reduction): one float4
    const int b_out  = bg * 4 + (q & 3);
    const int c4loc  = cG * 2 + (q >> 2);      // float4 index within 64-col slice

    // w pointers: Wt[cG*8 + c8][q*64 ...] -> 16B units
    const ulonglong2* wp[8];
#pragma unroll
    for (int c8 = 0; c8 < 8; c8++)
        wp[c8] = reinterpret_cast<const ulonglong2*>(
            Wt + (cG * 8 + c8) * WROW + q * 68);

    float* stSlot = stage + b_out * 68 + c4loc * 4;

    const float4* xptr = g_xproj4 + (size_t)(gb0 + b_out) * T_ * (H_ / 4)
                         + rank * 16 + c4loc;
    float4* hptr = g_hist4 + (size_t)(gb0 + b_out) * T_ * (H_ / 4)
                         + rank * 16 + c4loc;
    float4 xpn = xptr[0];

    uint32_t phF0 = 0, phF1 = 0, phE0 = 0, phE1 = 0;

    for (int t = 0; t < T_; t++) {
        const int cur = t & 1;
        const int nxt = cur ^ 1;

        if (t > 0) {
            if (cur == 0) { mbar_wait(fullBar0, phF0); if (tid == 0) MBAR_ARRIVE_EXPECT_TX(fullBar0, FULL_TX); phF0 ^= 1; }
            else          { mbar_wait(fullBar1, phF1); if (tid == 0) MBAR_ARRIVE_EXPECT_TX(fullBar1, FULL_TX); phF1 ^= 1; }
        }

        float4 xp = xpn;
        if (t + 1 < T_) xpn = xptr[(size_t)(t + 1) * (H_ / 4)];

        // ---- rec GEMM: 4b x 8c x 64k register tile ----
        const float* hbq = inb + cur * INBUF + q * INBSTRIDE;
        const ulonglong2* hp0 = reinterpret_cast<const ulonglong2*>(hbq + (bg * 4 + 0) * 68);
        const ulonglong2* hp1 = reinterpret_cast<const ulonglong2*>(hbq + (bg * 4 + 1) * 68);
        const ulonglong2* hp2 = reinterpret_cast<const ulonglong2*>(hbq + (bg * 4 + 2) * 68);
        const ulonglong2* hp3 = reinterpret_cast<const ulonglong2*>(hbq + (bg * 4 + 3) * 68);

        unsigned long long acc[4][8];
#pragma unroll
        for (int i = 0; i < 4; i++)
#pragma unroll
            for (int c8 = 0; c8 < 8; c8++) acc[i][c8] = 0ull;

#pragma unroll 2
        for (int j = 0; j < 16; j++) {
            ulonglong2 Hv[4];
            Hv[0] = hp0[j]; Hv[1] = hp1[j]; Hv[2] = hp2[j]; Hv[3] = hp3[j];
#pragma unroll
            for (int c8 = 0; c8 < 8; c8++) {
                ulonglong2 Wv = wp[c8][j];
#pragma unroll
                for (int i = 0; i < 4; i++) {
                    acc[i][c8] = fma2(Hv[i].x, Wv.x, acc[i][c8]);
                    acc[i][c8] = fma2(Hv[i].y, Wv.y, acc[i][c8]);
                }
            }
        }

        // ---- reduce-scatter butterfly over q (masks 1,2,4) ----
        unsigned long long r1[2][8];
        {
            const bool p = (q & 1);
#pragma unroll
            for (int ii = 0; ii < 2; ii++)
#pragma unroll
                for (int c8 = 0; c8 < 8; c8++) {
                    unsigned long long a0 = acc[2 * ii][c8];
                    unsigned long long a1 = acc[2 * ii + 1][c8];
                    unsigned long long snd = p ? a0 : a1;
                    unsigned long long rcv = __shfl_xor_sync(0xffffffffu, snd, 1);
                    r1[ii][c8] = p ? add2(a1, rcv) : add2(a0, rcv);
                }
        }
        unsigned long long r2[8];
        {
            const bool p = (q & 2);
#pragma unroll
            for (int c8 = 0; c8 < 8; c8++) {
                unsigned long long a0 = r1[0][c8];
                unsigned long long a1 = r1[1][c8];
                unsigned long long snd = p ? a0 : a1;
                unsigned long long rcv = __shfl_xor_sync(0xffffffffu, snd, 2);
                r2[c8] = p ? add2(a1, rcv) : add2(a0, rcv);
            }
        }
        unsigned long long fr[4];
        {
            const bool p = (q & 4);
#pragma unroll
            for (int c4 = 0; c4 < 4; c4++) {
                unsigned long long a0 = r2[c4];
                unsigned long long a1 = r2[4 + c4];
                unsigned long long snd = p ? a0 : a1;
                unsigned long long rcv = __shfl_xor_sync(0xffffffffu, snd, 4);
                fr[c4] = p ? add2(a1, rcv) : add2(a0, rcv);
            }
        }

        float lo0, hi0, lo1, hi1, lo2, hi2, lo3, hi3;
        unpack2(fr[0], lo0, hi0);
        unpack2(fr[1], lo1, hi1);
        unpack2(fr[2], lo2, hi2);
        unpack2(fr[3], lo3, hi3);

        float4 hn;
        hn.x = tanh_fast(lo0 + hi0 + xp.x);
        hn.y = tanh_fast(lo1 + hi1 + xp.y);
        hn.z = tanh_fast(lo2 + hi2 + xp.z);
        hn.w = tanh_fast(lo3 + hi3 + xp.w);

        // ---- guard: previous step's bulk copies finished READING stage ----
        if (tid < CLUSTER)
            asm volatile("cp.async.bulk.wait_group.read 0;" ::: "memory");
        __syncthreads();   // also: all threads done reading in[cur]

        *reinterpret_cast<float4*>(stSlot) = hn;
        hptr[(size_t)t * (H_ / 4)] = hn;
        __syncthreads();   // stage complete

        if (tid < CLUSTER) {
            const uint32_t r = (uint32_t)tid;   // thread r handles rank r
            uint32_t eb = (cur == 0) ? emptyBar0 : emptyBar1;
            MBAR_ARRIVE_REMOTE(eb, r);
            if (t < T_ - 1) {
                if (t >= 1) {
                    if (nxt == 0) { mbar_wait(emptyBar0, phE0); phE0 ^= 1; }
                    else          { mbar_wait(emptyBar1, phE1); phE1 ^= 1; }
                }
                asm volatile("fence.proxy.async.shared::cta;" ::: "memory");
                uint32_t dstLocal = smem_base +
                    (OFF_IN + nxt * INBUF + (int)rank * INBSTRIDE) * 4;
                uint32_t fb = (nxt == 0) ? fullBar0 : fullBar1;
                uint32_t dst = mapa_u32(dstLocal, r);
                uint32_t mb  = mapa_u32(fb, r);
                asm volatile(
                    "cp.async.bulk.shared::cluster.shared::cta"
                    ".mbarrier::complete_tx::bytes [%0], [%1], %2, [%3];"
                    :: "r"(dst), "r"(stageAddr), "r"(SLICE_BYTES), "r"(mb)
                    : "memory");
                asm volatile("cp.async.bulk.commit_group;" ::: "memory");
            }
        }
    }

    CLUSTER_SYNC_ASM();
}

// ---------------------------------------------------------------------------
// Kernel 3: out[bt][o] = g_hist[bt][:] @ Wout + bout   ([131072,512]@[512,64])
// ---------------------------------------------------------------------------
__global__ __launch_bounds__(256) void out_gemm_kernel(
    const float* __restrict__ Wout, const float* __restrict__ bout,
    float* __restrict__ out)
{
    extern __shared__ float smx[];
    float* Ast = smx;
    float* Bs  = smx + 8192;

    const int tid = threadIdx.x;
    const int bt0 = blockIdx.x * 64;
    const int ty = tid >> 4, tx = tid & 15;

    const float4* A4 = g_hist4;
    const float4* W4 = reinterpret_cast<const float4*>(Wout);

    unsigned long long a01[4] = {0ull, 0ull, 0ull, 0ull};
    unsigned long long a23[4] = {0ull, 0ull, 0ull, 0ull};

    for (int kc = 0; kc < H_ / 128; kc++) {
#pragma unroll
        for (int i = 0; i < 8; i++) {
            int lin = i * 256 + tid;
            int r = lin >> 5, kq = lin & 31;
            float4 v = A4[(size_t)(bt0 + r) * (H_ / 4) + kc * 32 + kq];
            int sw = (((r >> 2) ^ (kq & 15)) << 2) + (r & 3);
            int base = kq * 256;
            Ast[base +   0 + sw] = v.x;
            Ast[base +  64 + sw] = v.y;
            Ast[base + 128 + sw] = v.z;
            Ast[base + 192 + sw] = v.w;
        }
#pragma unroll
        for (int i = 0; i < 8; i++) {
            int lin = i * 256 + tid;
            int k = lin >> 4, nq = lin & 15;
            *reinterpret_cast<float4*>(&Bs[k * 64 + nq * 4]) =
                W4[(size_t)(kc * 128 + k) * (DOUT / 4) + nq];
        }
        __syncthreads();

#pragma unroll 8
        for (int k = 0; k < 128; k++) {
            int kg = (k >> 2) & 15;
            float4 a = *reinterpret_cast<const float4*>(
                &Ast[k * 64 + ((ty ^ kg) << 2)]);
            ulonglong2 bv = *reinterpret_cast<const ulonglong2*>(
                &Bs[k * 64 + tx * 4]);
            unsigned long long s0 = bcast2(a.x), s1 = bcast2(a.y),
                               s2 = bcast2(a.z), s3 = bcast2(a.w);
            a01[0] = fma2(s0, bv.x, a01[0]);  a23[0] = fma2(s0, bv.y, a23[0]);
            a01[1] = fma2(s1, bv.x, a01[1]);  a23[1] = fma2(s1, bv.y, a23[1]);
            a01[2] = fma2(s2, bv.x, a01[2]);  a23[2] = fma2(s2, bv.y, a23[2]);
            a01[3] = fma2(s3, bv.x, a01[3]);  a23[3] = fma2(s3, bv.y, a23[3]);
        }
        __syncthreads();
    }

    const float4 br = *reinterpret_cast<const float4*>(bout + tx * 4);
    float4* O4 = reinterpret_cast<float4*>(out);
#pragma unroll
    for (int i = 0; i < 4; i++) {
        float f0, f1, f2, f3;
        unpack2(a01[i], f0, f1);
        unpack2(a23[i], f2, f3);
        float4 o;
        o.x = f0 + br.x; o.y = f1 + br.y; o.z = f2 + br.z; o.w = f3 + br.w;
        O4[(size_t)(bt0 + ty * 4 + i) * (DOUT / 4) + tx] = o;
    }
}

// ---------------------------------------------------------------------------
extern "C" void kernel_launch(void* const* d_in, const int* in_sizes, int n_in,
                              void* d_out, int out_size)
{
    (void)in_sizes; (void)n_in; (void)out_size;
    const float* X    = (const float*)d_in[0];
    const float* Win  = (const float*)d_in[1];
    const float* Wrec = (const float*)d_in[2];
    const float* brec = (const float*)d_in[3];
    const float* Wout = (const float*)d_in[4];
    const float* bout = (const float*)d_in[5];
    const float* h0   = (const float*)d_in[6];
    float* out = (float*)d_out;

    cudaFuncSetAttribute(xproj_kernel,
        cudaFuncAttributeMaxDynamicSharedMemorySize, 65536);
    cudaFuncSetAttribute(rnn_kernel,
        cudaFuncAttributeMaxDynamicSharedMemorySize, SMEM_RNN_BYTES);
    cudaFuncSetAttribute(out_gemm_kernel,
        cudaFuncAttributeMaxDynamicSharedMemorySize, 65536);

    dim3 g1(B_ * T_ / 64, H_ / 64);
    xproj_kernel<<<g1, 256, 65536>>>(X, Win, brec);

    rnn_kernel<<<(B_ / BB) * CLUSTER, 256, SMEM_RNN_BYTES>>>(Wrec, h0);

    out_gemm_kernel<<<B_ * T_ / 64, 256, 65536>>>(Wout, bout, out);
}